// round 3
// baseline (speedup 1.0000x reference)
#include <cuda_runtime.h>

#define BATCH 2
#define SEQ   2048
#define HID   1024
#define NHEAD 16
#define HDIM  64

// Scratch: Q/K/V in [b][head][s][d] layout, 16 MB each.
__device__ float g_q[BATCH * NHEAD * SEQ * HDIM];
__device__ float g_k[BATCH * NHEAD * SEQ * HDIM];
__device__ float g_v[BATCH * NHEAD * SEQ * HDIM];

// ---------------------------------------------------------------------------
// Fused QKV projection: out[m][n] = sum_k X[m][k] * W[k][n] + b[n]
// Block tile 64(M) x 64(N), k-chunk 16, 256 threads, 4x4 micro-tile.
// N-tile of 64 == one head, so epilogue writes contiguous [b][h][s][d] float4s.
// ---------------------------------------------------------------------------
__global__ __launch_bounds__(256)
void qkv_kernel(const float* __restrict__ X,
                const float* __restrict__ Wq, const float* __restrict__ bq,
                const float* __restrict__ Wk, const float* __restrict__ bk,
                const float* __restrict__ Wv, const float* __restrict__ bv)
{
    const float* W; const float* bias; float* out;
    if (blockIdx.z == 0)      { W = Wq; bias = bq; out = g_q; }
    else if (blockIdx.z == 1) { W = Wk; bias = bk; out = g_k; }
    else                      { W = Wv; bias = bv; out = g_v; }

    __shared__ float As[64][20];   // 64 rows x 16 k (pad 20 -> 16B aligned, spread banks)
    __shared__ float Bs[16][64];   // 16 k x 64 n

    const int m0  = blockIdx.y * 64;
    const int n0  = blockIdx.x * 64;
    const int tid = threadIdx.x;
    const int ty  = tid >> 4;      // 0..15
    const int tx  = tid & 15;      // 0..15

    float acc[4][4];
#pragma unroll
    for (int i = 0; i < 4; i++)
#pragma unroll
        for (int j = 0; j < 4; j++) acc[i][j] = 0.f;

    const int ar = tid >> 2;           // 0..63
    const int ac = (tid & 3) << 2;     // 0,4,8,12
    const int bkk = tid >> 4;          // 0..15
    const int bc  = (tid & 15) << 2;   // 0..60

    for (int k0 = 0; k0 < HID; k0 += 16) {
        float4 av  = *(const float4*)&X[(size_t)(m0 + ar) * HID + k0 + ac];
        float4 wv4 = *(const float4*)&W[(size_t)(k0 + bkk) * HID + n0 + bc];
        *(float4*)&As[ar][ac] = av;
        *(float4*)&Bs[bkk][bc] = wv4;
        __syncthreads();

#pragma unroll
        for (int kk = 0; kk < 16; kk++) {
            float4 b4 = *(float4*)&Bs[kk][tx << 2];
            float a0 = As[ty * 4 + 0][kk];
            float a1 = As[ty * 4 + 1][kk];
            float a2 = As[ty * 4 + 2][kk];
            float a3 = As[ty * 4 + 3][kk];
            acc[0][0] += a0 * b4.x; acc[0][1] += a0 * b4.y; acc[0][2] += a0 * b4.z; acc[0][3] += a0 * b4.w;
            acc[1][0] += a1 * b4.x; acc[1][1] += a1 * b4.y; acc[1][2] += a1 * b4.z; acc[1][3] += a1 * b4.w;
            acc[2][0] += a2 * b4.x; acc[2][1] += a2 * b4.y; acc[2][2] += a2 * b4.z; acc[2][3] += a2 * b4.w;
            acc[3][0] += a3 * b4.x; acc[3][1] += a3 * b4.y; acc[3][2] += a3 * b4.z; acc[3][3] += a3 * b4.w;
        }
        __syncthreads();
    }

    const int head = n0 >> 6;
    float4 bb = *(const float4*)&bias[n0 + (tx << 2)];
#pragma unroll
    for (int i = 0; i < 4; i++) {
        int m = m0 + ty * 4 + i;
        int b = m / SEQ;
        int s = m - b * SEQ;
        float4 o;
        o.x = acc[i][0] + bb.x;
        o.y = acc[i][1] + bb.y;
        o.z = acc[i][2] + bb.z;
        o.w = acc[i][3] + bb.w;
        *(float4*)&out[(((size_t)(b * NHEAD + head)) * SEQ + s) * HDIM + (tx << 2)] = o;
    }
}

// ---------------------------------------------------------------------------
// Flash attention, fp32. One block = (64 q-rows, one (b,head)). K/V tiles of 32.
// 256 threads: ty=tid/16 owns q-rows ty*4..ty*4+3, tx=tid%16.
// Score cols per thread: c = tx + 16j, j in {0,1}  (conflict-free Ks reads).
// Output dims per thread: dd = tx*4..tx*4+3       (float4 Vs reads + stores).
// ---------------------------------------------------------------------------
__global__ __launch_bounds__(256)
void attn_kernel(const float* __restrict__ mask, float* __restrict__ out)
{
    __shared__ float Qs[64][64];   // q-rows x d
    __shared__ float Ks[32][68];   // k-rows x d (pad 68 for strided kv reads)
    __shared__ float Vs[32][64];   // k-rows x d
    __shared__ float Ps[64][33];   // probs: q-rows x k-cols (scalar access only)
    __shared__ float msk[32];

    const int q0   = blockIdx.x * 64;
    const int bh   = blockIdx.y;          // b*16 + head
    const int b    = bh >> 4;
    const int head = bh & 15;
    const float* Q = g_q + (size_t)bh * SEQ * HDIM;
    const float* K = g_k + (size_t)bh * SEQ * HDIM;
    const float* V = g_v + (size_t)bh * SEQ * HDIM;
    const float* mrow = mask + b * SEQ;   // [B,1,1,S]

    const int tid = threadIdx.x;
    const int ty  = tid >> 4;
    const int tx  = tid & 15;

    // Load Q tile (64x64)
#pragma unroll
    for (int it = 0; it < 4; it++) {
        int r = ty + it * 16;
        *(float4*)&Qs[r][tx << 2] =
            *(const float4*)&Q[(size_t)(q0 + r) * HDIM + (tx << 2)];
    }

    float m_i[4], l_i[4], acc[4][4];
#pragma unroll
    for (int i = 0; i < 4; i++) {
        m_i[i] = -1e30f;
        l_i[i] = 0.f;
#pragma unroll
        for (int j = 0; j < 4; j++) acc[i][j] = 0.f;
    }

    for (int kt = 0; kt < SEQ / 32; kt++) {
        const int k0 = kt * 32;
        __syncthreads();   // previous iter's Ks/Vs/Ps readers done
#pragma unroll
        for (int it = 0; it < 2; it++) {
            int r = ty + it * 16;   // 0..31
            *(float4*)&Ks[r][tx << 2] =
                *(const float4*)&K[(size_t)(k0 + r) * HDIM + (tx << 2)];
            *(float4*)&Vs[r][tx << 2] =
                *(const float4*)&V[(size_t)(k0 + r) * HDIM + (tx << 2)];
        }
        if (tid < 32) msk[tid] = mrow[k0 + tid];
        __syncthreads();

        // ---- scores: s[i][j] = Q[r0+i] . K[tx+16j]
        float s[4][2];
#pragma unroll
        for (int i = 0; i < 4; i++) { s[i][0] = 0.f; s[i][1] = 0.f; }

#pragma unroll
        for (int kk4 = 0; kk4 < 16; kk4++) {
            float4 qv[4], kv[2];
#pragma unroll
            for (int i = 0; i < 4; i++)
                qv[i] = *(float4*)&Qs[ty * 4 + i][kk4 << 2];
            kv[0] = *(float4*)&Ks[tx][kk4 << 2];
            kv[1] = *(float4*)&Ks[tx + 16][kk4 << 2];
#pragma unroll
            for (int i = 0; i < 4; i++) {
#pragma unroll
                for (int j = 0; j < 2; j++) {
                    s[i][j] += qv[i].x * kv[j].x + qv[i].y * kv[j].y
                             + qv[i].z * kv[j].z + qv[i].w * kv[j].w;
                }
            }
        }

        // ---- online softmax (row stats reduced over the 16 tx lanes)
#pragma unroll
        for (int i = 0; i < 4; i++) {
            float tmax = -1e30f;
#pragma unroll
            for (int j = 0; j < 2; j++) {
                s[i][j] = s[i][j] * 0.125f + msk[tx + (j << 4)];
                tmax = fmaxf(tmax, s[i][j]);
            }
#pragma unroll
            for (int o = 8; o >= 1; o >>= 1)
                tmax = fmaxf(tmax, __shfl_xor_sync(0xffffffffu, tmax, o));
            float mnew = fmaxf(m_i[i], tmax);
            float corr = __expf(m_i[i] - mnew);
            float psum = 0.f;
#pragma unroll
            for (int j = 0; j < 2; j++) {
                float p = __expf(s[i][j] - mnew);
                s[i][j] = p;
                psum += p;
            }
#pragma unroll
            for (int o = 8; o >= 1; o >>= 1)
                psum += __shfl_xor_sync(0xffffffffu, psum, o);
            l_i[i] = l_i[i] * corr + psum;
            m_i[i] = mnew;
#pragma unroll
            for (int j = 0; j < 4; j++) acc[i][j] *= corr;
        }

        // ---- stage P, then PV
#pragma unroll
        for (int i = 0; i < 4; i++) {
            Ps[ty * 4 + i][tx]      = s[i][0];
            Ps[ty * 4 + i][tx + 16] = s[i][1];
        }
        __syncthreads();

#pragma unroll 8
        for (int c = 0; c < 32; c++) {
            float4 vv = *(float4*)&Vs[c][tx << 2];
            float p0 = Ps[ty * 4 + 0][c];
            float p1 = Ps[ty * 4 + 1][c];
            float p2 = Ps[ty * 4 + 2][c];
            float p3 = Ps[ty * 4 + 3][c];
            acc[0][0] += p0 * vv.x; acc[0][1] += p0 * vv.y; acc[0][2] += p0 * vv.z; acc[0][3] += p0 * vv.w;
            acc[1][0] += p1 * vv.x; acc[1][1] += p1 * vv.y; acc[1][2] += p1 * vv.z; acc[1][3] += p1 * vv.w;
            acc[2][0] += p2 * vv.x; acc[2][1] += p2 * vv.y; acc[2][2] += p2 * vv.z; acc[2][3] += p2 * vv.w;
            acc[3][0] += p3 * vv.x; acc[3][1] += p3 * vv.y; acc[3][2] += p3 * vv.z; acc[3][3] += p3 * vv.w;
        }
    }

    // ---- epilogue: out[b][s][head*64+dd] = acc / l
#pragma unroll
    for (int i = 0; i < 4; i++) {
        float inv = 1.0f / l_i[i];
        int srow = q0 + ty * 4 + i;
        float4 o;
        o.x = acc[i][0] * inv;
        o.y = acc[i][1] * inv;
        o.z = acc[i][2] * inv;
        o.w = acc[i][3] * inv;
        *(float4*)&out[((size_t)(b * SEQ + srow)) * HID + head * HDIM + (tx << 2)] = o;
    }
}

extern "C" void kernel_launch(void* const* d_in, const int* in_sizes, int n_in,
                              void* d_out, int out_size)
{
    const float* hs  = (const float*)d_in[0];
    const float* msk = (const float*)d_in[1];
    const float* Wq  = (const float*)d_in[2];
    const float* bq  = (const float*)d_in[3];
    const float* Wk  = (const float*)d_in[4];
    const float* bk  = (const float*)d_in[5];
    const float* Wv  = (const float*)d_in[6];
    const float* bv  = (const float*)d_in[7];
    float* out = (float*)d_out;

    // QKV projections: grid (N/64, M/64, 3)
    qkv_kernel<<<dim3(HID / 64, (BATCH * SEQ) / 64, 3), 256>>>(
        hs, Wq, bq, Wk, bk, Wv, bv);

    // Attention: grid (S/64 q-tiles, B*NHEAD)
    attn_kernel<<<dim3(SEQ / 64, BATCH * NHEAD), 256>>>(msk, out);
}

// round 8
// speedup vs baseline: 1.1938x; 1.1938x over previous
#include <cuda_runtime.h>

#define BATCH 2
#define SEQ   2048
#define HID   1024
#define NHEAD 16
#define HDIM  64

typedef unsigned long long ull;

// Scratch: Q/K/V in [b][head][s][d] layout, 16 MB each.
__device__ float g_q[BATCH * NHEAD * SEQ * HDIM];
__device__ float g_k[BATCH * NHEAD * SEQ * HDIM];
__device__ float g_v[BATCH * NHEAD * SEQ * HDIM];

// ---------------------------------------------------------------------------
// f32x2 packed-math helpers (sm_103a FFMA2 — only reachable via PTX)
// ---------------------------------------------------------------------------
__device__ __forceinline__ void fma2(ull& d, ull a, ull b) {
    asm volatile("fma.rn.f32x2 %0, %1, %2, %0;" : "+l"(d) : "l"(a), "l"(b));
}
__device__ __forceinline__ void mul2(ull& d, ull a, ull b) {
    asm volatile("mul.rn.f32x2 %0, %1, %2;" : "=l"(d) : "l"(a), "l"(b));
}
__device__ __forceinline__ ull pack2(float s) {
    ull r;
    asm volatile("mov.b64 %0, {%1, %1};" : "=l"(r) : "f"(s));
    return r;
}
__device__ __forceinline__ void unpack2(ull v, float& lo, float& hi) {
    asm volatile("mov.b64 {%0, %1}, %2;" : "=f"(lo), "=f"(hi) : "l"(v));
}
// 16B shared load straight into two 64-bit regs (two f32x2 operands)
__device__ __forceinline__ void lds2(ull& x, ull& y, const float* p) {
    unsigned a = (unsigned)__cvta_generic_to_shared((const void*)p);
    asm volatile("ld.shared.v2.u64 {%0, %1}, [%2];" : "=l"(x), "=l"(y) : "r"(a));
}

// ---------------------------------------------------------------------------
// Fused QKV projection with FFMA2.
// Block tile 128(M) x 128(N), K-chunk 16, 256 threads.
// Per-thread micro-tile: 8 M-rows (as 4 packed pairs) x 8 N-cols (tx+16u).
// A staged k-transposed in smem so M-pairs load as ld.shared.v2.u64;
// B operand is a broadcast scalar packed {b,b}.
// ---------------------------------------------------------------------------
__global__ __launch_bounds__(256, 2)
void qkv_kernel(const float* __restrict__ X,
                const float* __restrict__ Wq, const float* __restrict__ bq,
                const float* __restrict__ Wk, const float* __restrict__ bk,
                const float* __restrict__ Wv, const float* __restrict__ bv)
{
    const float* W; const float* bias; float* out;
    if (blockIdx.z == 0)      { W = Wq; bias = bq; out = g_q; }
    else if (blockIdx.z == 1) { W = Wk; bias = bk; out = g_k; }
    else                      { W = Wv; bias = bv; out = g_v; }

    __shared__ float At[16][128];   // A transposed: [kk][m]
    __shared__ float Bs[16][128];   // B natural:    [kk][n]

    const int m0  = blockIdx.y * 128;
    const int n0  = blockIdx.x * 128;
    const int tid = threadIdx.x;
    const int ty  = tid >> 4;       // 0..15
    const int tx  = tid & 15;       // 0..15

    // A loader: 2 lanes per row (32B contiguous per row), rows tid>>1
    const int arow = tid >> 1;            // 0..127
    const int ak   = (tid & 1) * 8;       // k offset 0 or 8
    // B loader: row kk = tid>>5 (+8), 4 cols per lane (512B contiguous rows)
    const int bkk  = tid >> 5;            // 0..7
    const int bcol = (tid & 31) << 2;     // 0..124

    ull acc[4][8];
#pragma unroll
    for (int p = 0; p < 4; p++)
#pragma unroll
        for (int u = 0; u < 8; u++) acc[p][u] = 0ull;

    // prefetch chunk 0
    float4 pa0, pa1, pb0, pb1;
    pa0 = *(const float4*)&X[(size_t)(m0 + arow) * HID + ak + 0];
    pa1 = *(const float4*)&X[(size_t)(m0 + arow) * HID + ak + 4];
    pb0 = *(const float4*)&W[(size_t)(bkk)     * HID + n0 + bcol];
    pb1 = *(const float4*)&W[(size_t)(bkk + 8) * HID + n0 + bcol];

    for (int k0 = 0; k0 < HID; k0 += 16) {
        // stage prefetched chunk to smem (A transposed)
        At[ak + 0][arow] = pa0.x; At[ak + 1][arow] = pa0.y;
        At[ak + 2][arow] = pa0.z; At[ak + 3][arow] = pa0.w;
        At[ak + 4][arow] = pa1.x; At[ak + 5][arow] = pa1.y;
        At[ak + 6][arow] = pa1.z; At[ak + 7][arow] = pa1.w;
        *(float4*)&Bs[bkk][bcol]     = pb0;
        *(float4*)&Bs[bkk + 8][bcol] = pb1;
        __syncthreads();

        const int kn = k0 + 16;
        if (kn < HID) {
            pa0 = *(const float4*)&X[(size_t)(m0 + arow) * HID + kn + ak + 0];
            pa1 = *(const float4*)&X[(size_t)(m0 + arow) * HID + kn + ak + 4];
            pb0 = *(const float4*)&W[(size_t)(kn + bkk)     * HID + n0 + bcol];
            pb1 = *(const float4*)&W[(size_t)(kn + bkk + 8) * HID + n0 + bcol];
        }

#pragma unroll
        for (int kk = 0; kk < 16; kk++) {
            ull a0, a1, a2, a3;
            lds2(a0, a1, &At[kk][ty * 8]);       // rows (8ty..8ty+3) as 2 pairs
            lds2(a2, a3, &At[kk][ty * 8 + 4]);   // rows (8ty+4..8ty+7)
#pragma unroll
            for (int u = 0; u < 8; u++) {
                ull b2 = pack2(Bs[kk][tx + 16 * u]);
                fma2(acc[0][u], a0, b2);
                fma2(acc[1][u], a1, b2);
                fma2(acc[2][u], a2, b2);
                fma2(acc[3][u], a3, b2);
            }
        }
        __syncthreads();
    }

    // epilogue: +bias, scatter into [b][head][s][d]
#pragma unroll
    for (int u = 0; u < 8; u++) {
        const int col  = n0 + tx + 16 * u;
        const int head = col >> 6;
        const int d    = col & 63;
        const float bb = bias[col];
#pragma unroll
        for (int p = 0; p < 4; p++) {
            float v0, v1;
            unpack2(acc[p][u], v0, v1);
            int m = m0 + ty * 8 + 2 * p;
            int b = m >> 11, s = m & 2047;
            out[(((size_t)(b * NHEAD + head)) * SEQ + s) * HDIM + d] = v0 + bb;
            m++; b = m >> 11; s = m & 2047;
            out[(((size_t)(b * NHEAD + head)) * SEQ + s) * HDIM + d] = v1 + bb;
        }
    }
}

// ---------------------------------------------------------------------------
// Flash attention with FFMA2. Block = 64 q-rows x one (b,head). KTILE = 64.
// 256 threads: ty = tid/16 owns q-rows 4ty..4ty+3, tx = tid%16.
// Scores: 4q x 4k (cols tx+16j), packed over the k-dim (contiguous pairs).
// PV: packed over d (acc pairs), P broadcast-packed {p,p}.
// Dynamic smem: Qs 64x64 | Ks 64x68 | Vs 64x64 | Ps 64x68 | msk 64  = 67840 B
// ---------------------------------------------------------------------------
#define QS(r,c) Qs[(r)*64+(c)]
#define KS(r,c) Ks[(r)*68+(c)]
#define VS(r,c) Vs[(r)*64+(c)]
#define PS(r,c) Ps[(r)*68+(c)]

__global__ __launch_bounds__(256, 2)
void attn_kernel(const float* __restrict__ mask, float* __restrict__ out)
{
    extern __shared__ float sm[];
    float* Qs  = sm;                              // 4096
    float* Ks  = sm + 4096;                       // 4352
    float* Vs  = sm + 4096 + 4352;                // 4096
    float* Ps  = sm + 4096 + 4352 + 4096;         // 4352
    float* msk = sm + 4096 + 4352 + 4096 + 4352;  // 64

    const int q0   = blockIdx.x * 64;
    const int bh   = blockIdx.y;
    const int b    = bh >> 4;
    const int head = bh & 15;
    const float* Q = g_q + (size_t)bh * SEQ * HDIM;
    const float* K = g_k + (size_t)bh * SEQ * HDIM;
    const float* V = g_v + (size_t)bh * SEQ * HDIM;
    const float* mrow = mask + b * SEQ;

    const int tid = threadIdx.x;
    const int ty  = tid >> 4;
    const int tx  = tid & 15;

    // load Q tile
#pragma unroll
    for (int it = 0; it < 4; it++) {
        int r = ty + it * 16;
        *(float4*)&QS(r, tx << 2) =
            *(const float4*)&Q[(size_t)(q0 + r) * HDIM + (tx << 2)];
    }

    ull acc2[4][2];
    float m_i[4], l_i[4];
#pragma unroll
    for (int i = 0; i < 4; i++) {
        m_i[i] = -1e30f; l_i[i] = 0.f;
        acc2[i][0] = 0ull; acc2[i][1] = 0ull;
    }

    for (int kt = 0; kt < SEQ / 64; kt++) {
        const int k0 = kt * 64;
        __syncthreads();   // previous iteration's Ks/Vs/Ps readers done
#pragma unroll
        for (int it = 0; it < 4; it++) {
            int r = ty + it * 16;
            *(float4*)&KS(r, tx << 2) =
                *(const float4*)&K[(size_t)(k0 + r) * HDIM + (tx << 2)];
            *(float4*)&VS(r, tx << 2) =
                *(const float4*)&V[(size_t)(k0 + r) * HDIM + (tx << 2)];
        }
        if (tid < 64) msk[tid] = mrow[k0 + tid];
        __syncthreads();

        // ---- scores: s2[i][j] accumulates (even,odd) k-dim partials
        ull s2[4][4];
#pragma unroll
        for (int i = 0; i < 4; i++)
#pragma unroll
            for (int j = 0; j < 4; j++) s2[i][j] = 0ull;

#pragma unroll
        for (int kk4 = 0; kk4 < 16; kk4++) {
            ull q[4][2];
#pragma unroll
            for (int i = 0; i < 4; i++)
                lds2(q[i][0], q[i][1], &QS(ty * 4 + i, kk4 << 2));
#pragma unroll
            for (int j = 0; j < 4; j++) {
                ull kv0, kv1;
                lds2(kv0, kv1, &KS(tx + 16 * j, kk4 << 2));
#pragma unroll
                for (int i = 0; i < 4; i++) {
                    fma2(s2[i][j], q[i][0], kv0);
                    fma2(s2[i][j], q[i][1], kv1);
                }
            }
        }

        // ---- online softmax (reduce over 16 tx lanes)
#pragma unroll
        for (int i = 0; i < 4; i++) {
            float sv[4];
            float tmax = -1e30f;
#pragma unroll
            for (int j = 0; j < 4; j++) {
                float lo, hi;
                unpack2(s2[i][j], lo, hi);
                sv[j] = (lo + hi) * 0.125f + msk[tx + 16 * j];
                tmax = fmaxf(tmax, sv[j]);
            }
#pragma unroll
            for (int o = 8; o >= 1; o >>= 1)
                tmax = fmaxf(tmax, __shfl_xor_sync(0xffffffffu, tmax, o));
            float mnew = fmaxf(m_i[i], tmax);
            float corr = __expf(m_i[i] - mnew);
            float psum = 0.f;
#pragma unroll
            for (int j = 0; j < 4; j++) {
                float p = __expf(sv[j] - mnew);
                sv[j] = p;
                psum += p;
            }
#pragma unroll
            for (int o = 8; o >= 1; o >>= 1)
                psum += __shfl_xor_sync(0xffffffffu, psum, o);
            l_i[i] = l_i[i] * corr + psum;
            m_i[i] = mnew;
            ull c2 = pack2(corr);
            mul2(acc2[i][0], acc2[i][0], c2);
            mul2(acc2[i][1], acc2[i][1], c2);
#pragma unroll
            for (int j = 0; j < 4; j++)
                PS(ty * 4 + i, tx + 16 * j) = sv[j];
        }
        __syncthreads();

        // ---- PV: acc2 packed over d pairs
#pragma unroll 4
        for (int c0 = 0; c0 < 64; c0 += 4) {
            float4 p4[4];
#pragma unroll
            for (int i = 0; i < 4; i++)
                p4[i] = *(float4*)&PS(ty * 4 + i, c0);
            ull v[4][2];
#pragma unroll
            for (int cc = 0; cc < 4; cc++)
                lds2(v[cc][0], v[cc][1], &VS(c0 + cc, tx << 2));
#pragma unroll
            for (int cc = 0; cc < 4; cc++) {
#pragma unroll
                for (int i = 0; i < 4; i++) {
                    float pv = (cc == 0) ? p4[i].x : (cc == 1) ? p4[i].y
                             : (cc == 2) ? p4[i].z : p4[i].w;
                    ull pp = pack2(pv);
                    fma2(acc2[i][0], pp, v[cc][0]);
                    fma2(acc2[i][1], pp, v[cc][1]);
                }
            }
        }
    }

    // ---- epilogue
#pragma unroll
    for (int i = 0; i < 4; i++) {
        float inv = 1.0f / l_i[i];
        float o0, o1, o2, o3;
        unpack2(acc2[i][0], o0, o1);
        unpack2(acc2[i][1], o2, o3);
        float4 o;
        o.x = o0 * inv; o.y = o1 * inv; o.z = o2 * inv; o.w = o3 * inv;
        int srow = q0 + ty * 4 + i;
        *(float4*)&out[((size_t)(b * SEQ + srow)) * HID + head * HDIM + (tx << 2)] = o;
    }
}

#define ATTN_SMEM_BYTES ((4096 + 4352 + 4096 + 4352 + 64) * 4)

extern "C" void kernel_launch(void* const* d_in, const int* in_sizes, int n_in,
                              void* d_out, int out_size)
{
    const float* hs  = (const float*)d_in[0];
    const float* msk = (const float*)d_in[1];
    const float* Wq  = (const float*)d_in[2];
    const float* bq  = (const float*)d_in[3];
    const float* Wk  = (const float*)d_in[4];
    const float* bk  = (const float*)d_in[5];
    const float* Wv  = (const float*)d_in[6];
    const float* bv  = (const float*)d_in[7];
    float* out = (float*)d_out;

    cudaFuncSetAttribute(attn_kernel,
                         cudaFuncAttributeMaxDynamicSharedMemorySize,
                         ATTN_SMEM_BYTES);

    // QKV projections: grid (N/128, M/128, 3)
    qkv_kernel<<<dim3(HID / 128, (BATCH * SEQ) / 128, 3), 256>>>(
        hs, Wq, bq, Wk, bk, Wv, bv);

    // Attention: grid (S/64 q-tiles, B*NHEAD)
    attn_kernel<<<dim3(SEQ / 64, BATCH * NHEAD), 256, ATTN_SMEM_BYTES>>>(msk, out);
}